// round 1
// baseline (speedup 1.0000x reference)
#include <cuda_runtime.h>
#include <cstdint>

// 2x nearest-neighbor upsample:
// in : [B=16, C=64, H=256, W=256] fp32
// out: [B,   C,    2H,     2W   ] fp32
//
// One thread handles one input float4 (4 consecutive input pixels along W),
// producing an 8-pixel x 2-row output patch (4 float4 stores).

static constexpr int W_IN   = 256;
static constexpr int W4_IN  = W_IN / 4;     // 64 float4 per input row
static constexpr int W_OUT  = 512;
static constexpr int W4_OUT = W_OUT / 4;    // 128 float4 per output row

__global__ __launch_bounds__(256)
void upsample2x_kernel(const float4* __restrict__ in, float4* __restrict__ out,
                       int n_in4)
{
    int idx = blockIdx.x * blockDim.x + threadIdx.x;
    if (idx >= n_in4) return;

    int row  = idx >> 6;          // idx / W4_IN   (combined b*c*h row index)
    int col4 = idx & (W4_IN - 1); // idx % W4_IN

    float4 v = in[idx];

    float4 a = make_float4(v.x, v.x, v.y, v.y);
    float4 b = make_float4(v.z, v.z, v.w, v.w);

    // Output row pair: rows 2*row and 2*row+1, each W4_OUT float4 wide.
    long o = (long)(row * 2) * W4_OUT + col4 * 2;

    out[o]              = a;
    out[o + 1]          = b;
    out[o + W4_OUT]     = a;
    out[o + W4_OUT + 1] = b;
}

extern "C" void kernel_launch(void* const* d_in, const int* in_sizes, int n_in,
                              void* d_out, int out_size)
{
    const float4* in  = (const float4*)d_in[0];
    float4*       out = (float4*)d_out;

    int n_elems = in_sizes[0];          // 16*64*256*256 = 67108864
    int n_in4   = n_elems / 4;          // 16777216

    int threads = 256;
    int blocks  = (n_in4 + threads - 1) / threads;
    upsample2x_kernel<<<blocks, threads>>>(in, out, n_in4);
}

// round 2
// speedup vs baseline: 1.1262x; 1.1262x over previous
#include <cuda_runtime.h>
#include <cstdint>

// 2x nearest-neighbor upsample, 256-bit (v8.f32) load/store variant.
// in : [16, 64, 256, 256] fp32 = 67108864 floats
// out: [16, 64, 512, 512] fp32
//
// One thread handles one 32-byte input chunk (8 consecutive input pixels
// along W), producing a 16-pixel x 2-row output patch:
//   1 x ld.global.v8.f32  +  4 x st.global.v8.f32
//
// Row geometry: input row = 256 floats = 32 chunks of 8.
//               output row = 512 floats.

static constexpr int W8_IN  = 32;   // 8-float chunks per input row
static constexpr int W_OUT  = 512;  // floats per output row

__global__ __launch_bounds__(256)
void upsample2x_v8_kernel(const float* __restrict__ in,
                          float* __restrict__ out,
                          int n8)
{
    int idx = blockIdx.x * blockDim.x + threadIdx.x;
    if (idx >= n8) return;

    int row  = idx >> 5;          // idx / 32  (combined b*c*h row index)
    int col8 = idx & (W8_IN - 1); // idx % 32

    const float* ip = in + (size_t)idx * 8;

    float f0, f1, f2, f3, f4, f5, f6, f7;
    asm volatile(
        "ld.global.v8.f32 {%0,%1,%2,%3,%4,%5,%6,%7}, [%8];"
        : "=f"(f0), "=f"(f1), "=f"(f2), "=f"(f3),
          "=f"(f4), "=f"(f5), "=f"(f6), "=f"(f7)
        : "l"(ip));

    float* op = out + (size_t)(row * 2) * W_OUT + (size_t)col8 * 16;

    // Row 0, first 8 outputs: f0 f0 f1 f1 f2 f2 f3 f3
    asm volatile(
        "st.global.v8.f32 [%0], {%1,%2,%3,%4,%5,%6,%7,%8};"
        :: "l"(op),
           "f"(f0), "f"(f0), "f"(f1), "f"(f1),
           "f"(f2), "f"(f2), "f"(f3), "f"(f3)
        : "memory");
    // Row 0, next 8 outputs: f4 f4 f5 f5 f6 f6 f7 f7
    asm volatile(
        "st.global.v8.f32 [%0], {%1,%2,%3,%4,%5,%6,%7,%8};"
        :: "l"(op + 8),
           "f"(f4), "f"(f4), "f"(f5), "f"(f5),
           "f"(f6), "f"(f6), "f"(f7), "f"(f7)
        : "memory");
    // Row 1 (duplicate)
    asm volatile(
        "st.global.v8.f32 [%0], {%1,%2,%3,%4,%5,%6,%7,%8};"
        :: "l"(op + W_OUT),
           "f"(f0), "f"(f0), "f"(f1), "f"(f1),
           "f"(f2), "f"(f2), "f"(f3), "f"(f3)
        : "memory");
    asm volatile(
        "st.global.v8.f32 [%0], {%1,%2,%3,%4,%5,%6,%7,%8};"
        :: "l"(op + W_OUT + 8),
           "f"(f4), "f"(f4), "f"(f5), "f"(f5),
           "f"(f6), "f"(f6), "f"(f7), "f"(f7)
        : "memory");
}

extern "C" void kernel_launch(void* const* d_in, const int* in_sizes, int n_in,
                              void* d_out, int out_size)
{
    const float* in  = (const float*)d_in[0];
    float*       out = (float*)d_out;

    int n_elems = in_sizes[0];          // 67108864
    int n8      = n_elems / 8;          // 8388608 threads

    int threads = 256;
    int blocks  = (n8 + threads - 1) / threads;
    upsample2x_v8_kernel<<<blocks, threads>>>(in, out, n8);
}